// round 10
// baseline (speedup 1.0000x reference)
#include <cuda_runtime.h>
#include <math.h>
#include <stdint.h>

#define BB   256   // batch
#define TT   512   // seq len
#define DD   64    // input size
#define HH   256   // hidden
#define G4H  1024  // 4*H

// ---------------- static device scratch (no runtime allocations) ----------------
__device__ float g_xw[(size_t)TT * BB * G4H];   // input projections (reused per layer)
__device__ float g_out0[(size_t)TT * BB * HH];  // layer-0 outputs
__device__ float g_hfin[BB * HH];               // final hidden state of layer 1

// packed f32x2 FMA (Blackwell FFMA2; PTX-only)
__device__ __forceinline__ void ffma2(double& acc, double a, double b) {
    asm("fma.rn.f32x2 %0, %1, %2, %3;" : "=d"(acc) : "d"(a), "d"(b), "d"(acc));
}
__device__ __forceinline__ float dsum(double d) {
    return __int_as_float(__double2loint(d)) + __int_as_float(__double2hiint(d));
}

// ---------------- input projection GEMM, f32x2-packed ----------------
// g_xw[m][n] = sum_k in[m][k] * W[n][k] + b1[n] + b2[n],  m = t*BB + b
// SRC==0: in = x, layout [b][t][d].  SRC==1: in = g_out0, row m contiguous.
// Smem stride 66 floats: 8B-aligned rows, conflict-free LDS.64 (2nn mod 32).
template<int K, int SRC>
__global__ __launch_bounds__(256)
void proj_kernel(const float* __restrict__ in,
                 const float* __restrict__ W,
                 const float* __restrict__ b1,
                 const float* __restrict__ b2)
{
    __shared__ __align__(16) float As[32][66];
    __shared__ __align__(16) float Ws[128][66];

    const int m0  = blockIdx.x * 32;
    const int n0  = blockIdx.y * 128;
    const int tid = threadIdx.x;        // 256 threads
    const int nn  = tid & 31;
    const int mg  = tid >> 5;           // 0..7

    double acc[4][4];
    #pragma unroll
    for (int i = 0; i < 4; i++)
        #pragma unroll
        for (int j = 0; j < 4; j++) acc[i][j] = 0.0;

    for (int k0 = 0; k0 < K; k0 += 64) {
        // stage A tile: 32 rows x 64 k, float2 granules
        for (int idx = tid; idx < 32 * 32; idx += 256) {
            int r  = idx >> 5;
            int kd = idx & 31;
            int m  = m0 + r;
            const float* src;
            if (SRC == 0) {
                int b = m & (BB - 1);
                int t = m >> 8;
                src = in + (size_t)(b * TT + t) * DD;
            } else {
                src = g_out0 + (size_t)m * K;
            }
            *(float2*)&As[r][kd * 2] = *(const float2*)(src + k0 + kd * 2);
        }
        // stage W tile: 128 rows x 64 k, float2 granules
        for (int idx = tid; idx < 128 * 32; idx += 256) {
            int r  = idx >> 5;
            int kd = idx & 31;
            *(float2*)&Ws[r][kd * 2] =
                *(const float2*)(W + (size_t)(n0 + r) * K + k0 + kd * 2);
        }
        __syncthreads();

        #pragma unroll 8
        for (int kk = 0; kk < 32; kk++) {
            double a[4], w[4];
            #pragma unroll
            for (int i = 0; i < 4; i++) a[i] = *(const double*)&As[mg * 4 + i][kk * 2];
            #pragma unroll
            for (int i = 0; i < 4; i++) w[i] = *(const double*)&Ws[nn + 32 * i][kk * 2];
            #pragma unroll
            for (int i = 0; i < 4; i++)
                #pragma unroll
                for (int j = 0; j < 4; j++)
                    ffma2(acc[i][j], a[i], w[j]);
        }
        __syncthreads();
    }

    #pragma unroll
    for (int i = 0; i < 4; i++) {
        int m = m0 + mg * 4 + i;
        #pragma unroll
        for (int j = 0; j < 4; j++) {
            int n = n0 + nn + 32 * j;
            g_xw[(size_t)m * G4H + n] = dsum(acc[i][j]) + b1[n] + b2[n];
        }
    }
}

// ---------------- fast MUFU-free math (fma/alu pipes only) ----------------
__device__ __forceinline__ float exp_fast(float x) {
    float y = x * 1.4426950408889634f;
    y = fminf(fmaxf(y, -126.0f), 126.0f);
    float t = y + 12582912.0f;                     // round-to-nearest magic
    int   n = __float_as_int(t) - 0x4B400000;
    float f = y - (t - 12582912.0f);               // f in [-0.5, 0.5]
    float p = 1.5403530393381609e-4f;
    p = fmaf(p, f, 1.3333558146428443e-3f);
    p = fmaf(p, f, 9.6181291076284772e-3f);
    p = fmaf(p, f, 5.5504108664821580e-2f);
    p = fmaf(p, f, 2.4022650695910071e-1f);
    p = fmaf(p, f, 6.9314718055994531e-1f);
    p = fmaf(p, f, 1.0f);
    float s = __int_as_float((n + 127) << 23);
    return p * s;
}
__device__ __forceinline__ float rcp_fast(float d) {
    float x = __int_as_float(0x7EF311C3 - __float_as_int(d));
    float r;
    r = fmaf(-d, x, 1.0f); x = fmaf(x, r, x);
    r = fmaf(-d, x, 1.0f); x = fmaf(x, r, x);
    r = fmaf(-d, x, 1.0f); x = fmaf(x, r, x);
    return x;
}
__device__ __forceinline__ float sigmoid_fast(float z) {
    return rcp_fast(1.0f + exp_fast(-z));
}
__device__ __forceinline__ float tanh_fast(float z) {
    float u = exp_fast(-2.0f * z);
    return (1.0f - u) * rcp_fast(1.0f + u);
}

// ---------------- persistent cluster-based LSTM layer (512 threads) ----------------
// Grid (8, 16): x = j-tile (cluster rank), y = b-tile.  16 warps / CTA.
// GEMM:     warp -> (kh = w&1 k-half, bh = (w>>1)&1 batch-half, rb = w>>2 row-block)
//           thread: 1 row (rb*32+lane) x 8 batches x 128 k, f32x2-packed.
// Partials gathered in Zs[2][128][17]; epilogue thread = (cg = j, bq = 1 batch).
// Whh slice (130 KB) smem-resident; c in registers (1/thread);
// h exchanged via DSMEM multicast + 1 cluster barrier per step.
#define WS_STRIDE 260
#define HS_STRIDE 264
#define ZS_STRIDE 17
#define WS_FLOATS (128 * WS_STRIDE)             // 33280
#define HS_FLOATS (2 * 16 * HS_STRIDE)          // 8448
#define ZS_FLOATS (2 * 128 * ZS_STRIDE)         // 4352
#define LSTM_SMEM_BYTES ((WS_FLOATS + HS_FLOATS + ZS_FLOATS) * 4)   // 184,320 B

__global__ __cluster_dims__(8, 1, 1) __launch_bounds__(512, 1)
void lstm_layer_kernel(const float* __restrict__ Whh, int write_out0)
{
    extern __shared__ __align__(16) float smem[];
    float* Ws = smem;                          // [128][WS_STRIDE], row r = g*32+jj
    float* Hs = smem + WS_FLOATS;              // [2][16][HS_STRIDE]
    float* Zs = smem + WS_FLOATS + HS_FLOATS;  // [2][128][ZS_STRIDE]

    const int tid  = threadIdx.x;              // 512 threads
    const int lane = tid & 31;
    const int warp = tid >> 5;                 // 0..15
    // GEMM mapping
    const int kh   = warp & 1;                 // k-half
    const int bh   = (warp >> 1) & 1;          // batch-half
    const int rb   = warp >> 2;                // row block 0..3
    const int r    = rb * 32 + lane;           // row = gate*32 + j
    const int kbase = kh * 128;
    const int bbase = bh * 8;
    // epilogue mapping
    const int cg   = lane;                     // j within tile
    const int bq   = warp;                     // one batch per warp
    const int by   = blockIdx.x;               // cluster rank (j-tile)
    const int bx   = blockIdx.y;               // b-tile
    const int j0   = by * 32;
    const int jg   = j0 + cg;
    const int b0   = bx * 16;

    // Stage Whh slice: smem row c = g*32+jj  <-  Whh row g*HH + j0 + jj
    for (int idx = tid; idx < 128 * 64; idx += 512) {
        int c   = idx >> 6;
        int kq  = idx & 63;
        int row = (c >> 5) * HH + j0 + (c & 31);
        float4 v = *(const float4*)(Whh + (size_t)row * HH + kq * 4);
        *(float4*)(Ws + c * WS_STRIDE + kq * 4) = v;
    }
    // Zero Hs buffer 0 (step 0 reads it; step 0 writes go to buffer 1)
    for (int idx = tid; idx < 16 * HS_STRIDE; idx += 512)
        Hs[idx] = 0.0f;
    __syncthreads();

    // Remote Hs base addresses for all 8 cluster ranks
    uint32_t hs_local;
    asm("{ .reg .u64 t; cvta.to.shared.u64 t, %1; cvt.u32.u64 %0, t; }"
        : "=r"(hs_local) : "l"(Hs));
    uint32_t peer[8];
    #pragma unroll
    for (int p = 0; p < 8; p++)
        asm("mapa.shared::cluster.u32 %0, %1, %2;"
            : "=r"(peer[p]) : "r"(hs_local), "r"(p));

    float creg = 0.0f;                         // c for (b0+bq, jg)

    asm volatile("barrier.cluster.arrive.aligned;" ::: "memory");
    asm volatile("barrier.cluster.wait.aligned;"   ::: "memory");

    const float* wrow = Ws + r * WS_STRIDE + kbase;

    for (int t = 0; t < TT; t++) {
        // Prefetch xw for this step's epilogue (issued early; DRAM latency hidden)
        const float* xw_b = g_xw + ((size_t)t * BB + (b0 + bq)) * G4H + jg;
        float xw0 = __ldg(xw_b + 0 * HH);
        float xw1 = __ldg(xw_b + 1 * HH);
        float xw2 = __ldg(xw_b + 2 * HH);
        float xw3 = __ldg(xw_b + 3 * HH);

        // ---- GEMM partial: z[r][bbase..bbase+8) over k-half ----
        const float* HsR = Hs + (t & 1) * (16 * HS_STRIDE) + kbase;
        double acc[8];
        #pragma unroll
        for (int b = 0; b < 8; b++) acc[b] = 0.0;

        #pragma unroll 2
        for (int k = 0; k < 128; k += 4) {
            double2 w = *(const double2*)(wrow + k);
            #pragma unroll
            for (int b = 0; b < 8; b++) {
                double2 h = *(const double2*)(HsR + (bbase + b) * HS_STRIDE + k);
                ffma2(acc[b], w.x, h.x);
                ffma2(acc[b], w.y, h.y);
            }
        }
        // store partials: Zs[kh][r][bbase+b]  (stride 17 -> conflict-free)
        float* zrow = Zs + (kh * 128 + r) * ZS_STRIDE + bbase;
        #pragma unroll
        for (int b = 0; b < 8; b++) zrow[b] = dsum(acc[b]);
        __syncthreads();

        // ---- epilogue: one (batch, j) per thread ----
        const int nb = (t + 1) & 1;
        const float* z0 = Zs + (0 * 32 + cg) * ZS_STRIDE + bq;
        const float* z1 = Zs + (1 * 32 + cg) * ZS_STRIDE + bq;
        const float* z2 = Zs + (2 * 32 + cg) * ZS_STRIDE + bq;
        const float* z3 = Zs + (3 * 32 + cg) * ZS_STRIDE + bq;
        const int ZH = 128 * ZS_STRIDE;

        float zi = z0[0] + z0[ZH] + xw0;
        float zf = z1[0] + z1[ZH] + xw1;
        float zg = z2[0] + z2[ZH] + xw2;
        float zo = z3[0] + z3[ZH] + xw3;

        float ig = sigmoid_fast(zi);
        float fg = sigmoid_fast(zf);
        float gg = tanh_fast(zg);
        float og = sigmoid_fast(zo);

        float cn = fmaf(fg, creg, ig * gg);
        float hn = og * tanh_fast(cn);
        creg = cn;

        // Multicast h into next-step buffer of all 8 cluster CTAs
        uint32_t off = (uint32_t)(((nb * 16 + bq) * HS_STRIDE + jg) * 4);
        #pragma unroll
        for (int p = 0; p < 8; p++)
            asm volatile("st.shared::cluster.f32 [%0], %1;"
                         :: "r"(peer[p] + off), "f"(hn) : "memory");

        if (write_out0)
            g_out0[((size_t)t * BB + (b0 + bq)) * HH + jg] = hn;
        else if (t == TT - 1)
            g_hfin[(b0 + bq) * HH + jg] = hn;

        // Orders DSMEM h-writes before next step's reads; also protects Zs reuse.
        asm volatile("barrier.cluster.arrive.aligned;" ::: "memory");
        asm volatile("barrier.cluster.wait.aligned;"   ::: "memory");
    }
}

// ---------------- final linear: out[b] = dot(h_last[b], Wf) + bf ----------------
__global__ __launch_bounds__(256)
void final_kernel(const float* __restrict__ Wf, const float* __restrict__ bf,
                  float* __restrict__ out)
{
    int warp = (blockIdx.x * blockDim.x + threadIdx.x) >> 5;
    int lane = threadIdx.x & 31;
    if (warp >= BB) return;
    const float* h = g_hfin + warp * HH;
    float s = 0.0f;
    for (int k = lane; k < HH; k += 32) s += h[k] * Wf[k];
    #pragma unroll
    for (int o = 16; o > 0; o >>= 1) s += __shfl_xor_sync(0xffffffffu, s, o);
    if (lane == 0) out[warp] = s + bf[0];
}

// ---------------- launch: 5 graph nodes total ----------------
extern "C" void kernel_launch(void* const* d_in, const int* in_sizes, int n_in,
                              void* d_out, int out_size)
{
    const float* x    = (const float*)d_in[0];
    const float* Wih0 = (const float*)d_in[1];
    const float* Whh0 = (const float*)d_in[2];
    const float* bih0 = (const float*)d_in[3];
    const float* bhh0 = (const float*)d_in[4];
    const float* Wih1 = (const float*)d_in[5];
    const float* Whh1 = (const float*)d_in[6];
    const float* bih1 = (const float*)d_in[7];
    const float* bhh1 = (const float*)d_in[8];
    const float* Wf   = (const float*)d_in[9];
    const float* bf   = (const float*)d_in[10];
    float* out = (float*)d_out;

    cudaFuncSetAttribute(lstm_layer_kernel,
                         cudaFuncAttributeMaxDynamicSharedMemorySize,
                         LSTM_SMEM_BYTES);

    const dim3 proj_grid(TT * BB / 32, G4H / 128);   // (4096, 8)
    const dim3 lstm_grid(8, 16);                     // 16 clusters of 8 CTAs

    proj_kernel<DD, 0><<<proj_grid, 256>>>(x, Wih0, bih0, bhh0);
    lstm_layer_kernel<<<lstm_grid, 512, LSTM_SMEM_BYTES>>>(Whh0, 1);

    proj_kernel<HH, 1><<<proj_grid, 256>>>(nullptr, Wih1, bih1, bhh1);
    lstm_layer_kernel<<<lstm_grid, 512, LSTM_SMEM_BYTES>>>(Whh1, 0);

    final_kernel<<<(BB * 32 + 255) / 256, 256>>>(Wf, bf, out);
}